// round 1
// baseline (speedup 1.0000x reference)
#include <cuda_runtime.h>
#include <math.h>

// Problem constants
#define S_TOK 8192
#define MDIM  4096
#define NEXP  64
#define CAP   128
#define NBLK  128            // S_TOK / 64
#define SEC   67108864ULL    // S_TOK * NEXP * CAP

// GEMM tiling
#define TM 64
#define TN 64
#define KB 32
#define LDP 68               // padded smem row stride (floats)

// ---------- scratch (device globals; fully overwritten each launch) ----------
__device__ int   g_eid[S_TOK];
__device__ float g_gate[S_TOK];
__device__ float g_me[NBLK * NEXP];    // per-block sum of gates per expert
__device__ int   g_cnt[NBLK * NEXP];   // per-block argmax histogram
__device__ int   g_offs[NBLK * NEXP];  // exclusive scan of g_cnt over blocks

// ---------------------------------------------------------------------------
// Kernel 1: 64x64 fp32 GEMM tile (K=4096) + fused softmax/argmax epilogue.
// Block b handles tokens [b*64, b*64+64). 256 threads, 4x4 register tile.
// ---------------------------------------------------------------------------
__global__ __launch_bounds__(256) void gemm_gate_kernel(
    const float* __restrict__ x, const float* __restrict__ wg)
{
    __shared__ float smem[2 * KB * LDP];   // sA | sB ; reused as logits [64][65]
    __shared__ int   s_eid[TM];

    const int t  = threadIdx.x;
    const int tx = t & 15;       // col group
    const int ty = t >> 4;       // row group
    const int b  = blockIdx.x;

    float acc[4][4];
    #pragma unroll
    for (int i = 0; i < 4; i++)
        #pragma unroll
        for (int j = 0; j < 4; j++) acc[i][j] = 0.f;

    const float* xblk = x + (size_t)b * TM * MDIM;
    float* sA = smem;
    float* sB = smem + KB * LDP;

    const int lrow = t >> 3;        // 0..31
    const int lc0  = (t & 7) * 4;   // 0..28

    for (int k0 = 0; k0 < MDIM; k0 += KB) {
        // load A (64 x 32) and B (64 x 32) tiles, transposed into [k][row]
        #pragma unroll
        for (int i = 0; i < 2; i++) {
            int row = lrow + i * 32;
            float4 va = *(const float4*)(xblk + (size_t)row * MDIM + k0 + lc0);
            sA[(lc0 + 0) * LDP + row] = va.x;
            sA[(lc0 + 1) * LDP + row] = va.y;
            sA[(lc0 + 2) * LDP + row] = va.z;
            sA[(lc0 + 3) * LDP + row] = va.w;
            float4 vb = *(const float4*)(wg + (size_t)row * MDIM + k0 + lc0);
            sB[(lc0 + 0) * LDP + row] = vb.x;
            sB[(lc0 + 1) * LDP + row] = vb.y;
            sB[(lc0 + 2) * LDP + row] = vb.z;
            sB[(lc0 + 3) * LDP + row] = vb.w;
        }
        __syncthreads();
        #pragma unroll 8
        for (int kk = 0; kk < KB; kk++) {
            float4 a = *(const float4*)&sA[kk * LDP + ty * 4];
            float4 c = *(const float4*)&sB[kk * LDP + tx * 4];
            float av[4] = {a.x, a.y, a.z, a.w};
            float bv[4] = {c.x, c.y, c.z, c.w};
            #pragma unroll
            for (int i = 0; i < 4; i++)
                #pragma unroll
                for (int j = 0; j < 4; j++) acc[i][j] += av[i] * bv[j];
        }
        __syncthreads();
    }

    // dump logits tile to shared, padded stride 65
    float* Ls = smem;   // [64][65]
    #pragma unroll
    for (int i = 0; i < 4; i++)
        #pragma unroll
        for (int j = 0; j < 4; j++)
            Ls[(ty * 4 + i) * 65 + (tx * 4 + j)] = acc[i][j];
    __syncthreads();

    // per-row softmax + argmax (64 rows by 64 threads)
    if (t < TM) {
        const int r = t;
        float m = -INFINITY; int am = 0;
        #pragma unroll 8
        for (int e = 0; e < NEXP; e++) {
            float v = Ls[r * 65 + e];
            if (v > m) { m = v; am = e; }
        }
        float sum = 0.f;
        #pragma unroll 8
        for (int e = 0; e < NEXP; e++) {
            float ex = expf(Ls[r * 65 + e] - m);
            Ls[r * 65 + e] = ex;
            sum += ex;
        }
        float inv = 1.f / sum;
        #pragma unroll 8
        for (int e = 0; e < NEXP; e++) Ls[r * 65 + e] *= inv;
        int s = b * TM + r;
        g_eid[s]  = am;
        g_gate[s] = inv;      // exp(l_max - m) = 1 -> gate = 1/sum
        s_eid[r]  = am;
    }
    __syncthreads();

    // per-expert column sums (me partials) + histogram
    if (t < NEXP) {
        const int e = t;
        float msum = 0.f; int cnt = 0;
        #pragma unroll 8
        for (int r = 0; r < TM; r++) {
            msum += Ls[r * 65 + e];
            cnt  += (s_eid[r] == e);
        }
        g_me[b * NEXP + e]  = msum;
        g_cnt[b * NEXP + e] = cnt;
    }
}

// ---------------------------------------------------------------------------
// Kernel 2: exclusive scan over 128 blocks per expert; exp_counts, l_aux.
// ---------------------------------------------------------------------------
__global__ void scan_kernel(float* __restrict__ out)
{
    __shared__ float s_val[NEXP];
    const int e = threadIdx.x;   // 64 threads
    float me_tot = 0.f; int run = 0;
    for (int b = 0; b < NBLK; b++) {
        g_offs[b * NEXP + e] = run;
        run    += g_cnt[b * NEXP + e];
        me_tot += g_me[b * NEXP + e];
    }
    out[1 + 2 * SEC + e] = (float)run;   // exp_counts (pre-drop)
    s_val[e] = me_tot * (float)run;
    __syncthreads();
    if (e == 0) {
        float acc = 0.f;
        for (int i = 0; i < NEXP; i++) acc += s_val[i];
        // l_aux = E/S^2 * sum(me_tot * cnt) ;  64/8192^2 = 1/1048576
        out[0] = acc * (1.f / 1048576.f);
    }
}

// ---------------------------------------------------------------------------
// Kernel 3: resolve in-order rank per token, scatter combine/dispatch.
// ---------------------------------------------------------------------------
__global__ void scatter_kernel(float* __restrict__ out)
{
    __shared__ int   s_eid[TM];
    __shared__ float s_g[TM];
    const int b = blockIdx.x;
    const int i = threadIdx.x;       // 64 threads
    const int s = b * TM + i;
    s_eid[i] = g_eid[s];
    s_g[i]   = g_gate[s];
    __syncthreads();
    const int e = s_eid[i];
    int rank = g_offs[b * NEXP + e];
    for (int j = 0; j < i; j++) rank += (s_eid[j] == e);
    if (rank < CAP) {
        size_t base = (size_t)s * (NEXP * CAP) + (size_t)e * CAP + rank;
        out[1 + base]       = s_g[i];   // combine_weights
        out[1 + SEC + base] = 1.0f;     // dispatch_mask (gate > 0 always)
    }
}

// ---------------------------------------------------------------------------
extern "C" void kernel_launch(void* const* d_in, const int* in_sizes, int n_in,
                              void* d_out, int out_size)
{
    const float* x  = (const float*)d_in[0];
    const float* wg = (const float*)d_in[1];
    float* out = (float*)d_out;

    // zero the entire output (sparse results + poisoned buffer)
    cudaMemsetAsync(d_out, 0, (size_t)out_size * sizeof(float), 0);

    gemm_gate_kernel<<<NBLK, 256>>>(x, wg);
    scan_kernel<<<1, NEXP>>>(out);
    scatter_kernel<<<NBLK, TM>>>(out);
}

// round 2
// speedup vs baseline: 1.6892x; 1.6892x over previous
#include <cuda_runtime.h>
#include <math.h>

// Problem constants
#define S_TOK 8192
#define MDIM  4096
#define NEXP  64
#define CAP   128
#define SEC   67108864ULL            // S*E*C
#define OUT_FLOATS 134217793ULL      // 1 + 2*SEC + 64
#define ZMAIN 134217728ULL           // floats zeroed by main pattern (33,554,432 float4)

// GEMM tiling
#define TILE_M 128                   // tokens per CTA
#define KB     32
#define KSPLIT 4
#define KCHUNK (MDIM / KSPLIT)       // 1024
#define NTB    (S_TOK / TILE_M)      // 64 token blocks
#define GRID_G (NTB * KSPLIT)        // 256 CTAs
#define THREADS 256
#define LDA 132                      // padded smem strides (floats)
#define LDB 68

#define NBLK64 (S_TOK / 64)          // 128 blocks for gate/scatter

typedef unsigned long long u64;

// ---------- scratch (device globals; fully overwritten each launch) ----------
__device__ float g_part[KSPLIT * S_TOK * NEXP];   // 8 MB partial logits
__device__ int   g_eid[S_TOK];
__device__ float g_gate[S_TOK];
__device__ float g_me[NBLK64 * NEXP];
__device__ int   g_cnt[NBLK64 * NEXP];
__device__ int   g_offs[NBLK64 * NEXP];

// packed f32x2 FMA (PTX-only; ptxas never auto-fuses)
__device__ __forceinline__ void ffma2(u64& d, u64 a, u64 b) {
    asm("fma.rn.f32x2 %0, %1, %2, %0;" : "+l"(d) : "l"(a), "l"(b));
}
__device__ __forceinline__ u64 dup2(float b) {
    u64 r; unsigned u = __float_as_uint(b);
    asm("mov.b64 %0, {%1, %1};" : "=l"(r) : "r"(u));
    return r;
}

// ---------------------------------------------------------------------------
// Kernel 1: 128x64 fp32 GEMM tile over a K/4 chunk, FFMA2 inner loop,
// fused zeroing of the 537MB output buffer (rides the idle memory pipe).
// ---------------------------------------------------------------------------
__global__ __launch_bounds__(THREADS) void gemm_zero_kernel(
    const float* __restrict__ x, const float* __restrict__ wg,
    float* __restrict__ out)
{
    __shared__ float sA[KB * LDA];
    __shared__ float sB[KB * LDB];

    const int t  = threadIdx.x;
    const int bx = blockIdx.x;
    const int tb = bx & (NTB - 1);     // token block
    const int kh = bx >> 6;            // k chunk (NTB == 64)
    const int tx = t & 15;             // col group: 4 experts
    const int ty = t >> 4;             // row group: 8 tokens

    u64 acc[4][4];                     // 4 row-pairs x 4 cols
    #pragma unroll
    for (int i = 0; i < 4; i++)
        #pragma unroll
        for (int j = 0; j < 4; j++) acc[i][j] = 0ULL;

    const float* xblk = x  + (size_t)tb * TILE_M * MDIM + (size_t)kh * KCHUNK;
    const float* wblk = wg + (size_t)kh * KCHUNK;

    float4* out4 = (float4*)out;
    const unsigned flat = bx * THREADS + t;   // 0..65535

    // staging assignments
    const int arow = t >> 1;           // 0..127
    const int acol = (t & 1) * 16;     // 0 or 16
    const int brow = t >> 2;           // 0..63
    const int bcol = (t & 3) * 8;      // 0,8,16,24

    #pragma unroll 1
    for (int s = 0; s < KCHUNK / KB; s++) {   // 32 steps
        const int k0 = s * KB;

        // stage A tile (128 x 32), transposed to [k][row]
        #pragma unroll
        for (int j = 0; j < 4; j++) {
            float4 v = *(const float4*)(xblk + (size_t)arow * MDIM + k0 + acol + j * 4);
            sA[(acol + j*4 + 0) * LDA + arow] = v.x;
            sA[(acol + j*4 + 1) * LDA + arow] = v.y;
            sA[(acol + j*4 + 2) * LDA + arow] = v.z;
            sA[(acol + j*4 + 3) * LDA + arow] = v.w;
        }
        // stage B tile (64 x 32), transposed to [k][expert]
        #pragma unroll
        for (int j = 0; j < 2; j++) {
            float4 v = *(const float4*)(wblk + (size_t)brow * MDIM + k0 + bcol + j * 4);
            sB[(bcol + j*4 + 0) * LDB + brow] = v.x;
            sB[(bcol + j*4 + 1) * LDB + brow] = v.y;
            sB[(bcol + j*4 + 2) * LDB + brow] = v.z;
            sB[(bcol + j*4 + 3) * LDB + brow] = v.w;
        }
        __syncthreads();

        // fused output zeroing: 16 coalesced float4 stores per thread per step
        {
            const float4 z = make_float4(0.f, 0.f, 0.f, 0.f);
            #pragma unroll
            for (int j = 0; j < 16; j++)
                out4[(size_t)(s * 16 + j) * 65536u + flat] = z;
        }

        // FFMA2 compute
        #pragma unroll 8
        for (int kk = 0; kk < KB; kk++) {
            ulonglong2 a01 = *(const ulonglong2*)&sA[kk * LDA + ty * 8];
            ulonglong2 a23 = *(const ulonglong2*)&sA[kk * LDA + ty * 8 + 4];
            float4 bv = *(const float4*)&sB[kk * LDB + tx * 4];
            u64 ar[4] = { a01.x, a01.y, a23.x, a23.y };
            u64 bd[4] = { dup2(bv.x), dup2(bv.y), dup2(bv.z), dup2(bv.w) };
            #pragma unroll
            for (int i = 0; i < 4; i++)
                #pragma unroll
                for (int j = 0; j < 4; j++)
                    ffma2(acc[i][j], ar[i], bd[j]);
        }
        __syncthreads();
    }

    // epilogue: write partial logits [kh][token][expert]
    float* part = g_part + (size_t)kh * S_TOK * NEXP + (size_t)tb * TILE_M * NEXP;
    #pragma unroll
    for (int i = 0; i < 4; i++) {
        const int r0 = ty * 8 + i * 2;
        float4 lo, hi;
        lo.x = __uint_as_float((unsigned)(acc[i][0]));
        lo.y = __uint_as_float((unsigned)(acc[i][1]));
        lo.z = __uint_as_float((unsigned)(acc[i][2]));
        lo.w = __uint_as_float((unsigned)(acc[i][3]));
        hi.x = __uint_as_float((unsigned)(acc[i][0] >> 32));
        hi.y = __uint_as_float((unsigned)(acc[i][1] >> 32));
        hi.z = __uint_as_float((unsigned)(acc[i][2] >> 32));
        hi.w = __uint_as_float((unsigned)(acc[i][3] >> 32));
        *(float4*)&part[(size_t)r0       * NEXP + tx * 4] = lo;
        *(float4*)&part[(size_t)(r0 + 1) * NEXP + tx * 4] = hi;
    }

    // tail zeros (last 65 floats not covered by the main pattern)
    if (bx == 0 && t < (int)(OUT_FLOATS - ZMAIN))
        out[ZMAIN + t] = 0.0f;
}

// ---------------------------------------------------------------------------
// Kernel 2: reduce K-split partials, softmax/argmax, per-block me/cnt.
// Block b handles tokens [b*64, b*64+64). 256 threads.
// ---------------------------------------------------------------------------
__global__ __launch_bounds__(256) void gate_kernel()
{
    __shared__ float Ls[64 * 65];
    __shared__ int   s_eid[64];
    const int b = blockIdx.x;        // 0..127
    const int t = threadIdx.x;
    const size_t off = (size_t)b * 64 * NEXP;

    // reduce the 4 partial planes (coalesced float4)
    #pragma unroll
    for (int i = 0; i < 4; i++) {
        const int idx4 = t + i * 256;     // 0..1023
        float4 v = *(const float4*)&g_part[off + (size_t)idx4 * 4];
        #pragma unroll
        for (int p = 1; p < KSPLIT; p++) {
            float4 w = *(const float4*)&g_part[(size_t)p * S_TOK * NEXP + off + (size_t)idx4 * 4];
            v.x += w.x; v.y += w.y; v.z += w.z; v.w += w.w;
        }
        const int r = (idx4 * 4) >> 6;
        const int e = (idx4 * 4) & 63;
        Ls[r * 65 + e + 0] = v.x;
        Ls[r * 65 + e + 1] = v.y;
        Ls[r * 65 + e + 2] = v.z;
        Ls[r * 65 + e + 3] = v.w;
    }
    __syncthreads();

    // per-row softmax + argmax
    if (t < 64) {
        const int r = t;
        float m = -INFINITY; int am = 0;
        #pragma unroll 8
        for (int e = 0; e < NEXP; e++) {
            float v = Ls[r * 65 + e];
            if (v > m) { m = v; am = e; }
        }
        float sum = 0.f;
        #pragma unroll 8
        for (int e = 0; e < NEXP; e++) {
            float ex = expf(Ls[r * 65 + e] - m);
            Ls[r * 65 + e] = ex;
            sum += ex;
        }
        const float inv = 1.f / sum;
        #pragma unroll 8
        for (int e = 0; e < NEXP; e++) Ls[r * 65 + e] *= inv;
        const int s = b * 64 + r;
        g_eid[s]  = am;
        g_gate[s] = inv;         // exp(max - max) = 1 -> gate = 1/sum
        s_eid[r]  = am;
    }
    __syncthreads();

    // per-expert column sums (me partials) + argmax histogram
    if (t < NEXP) {
        const int e = t;
        float msum = 0.f; int cnt = 0;
        #pragma unroll 8
        for (int r = 0; r < 64; r++) {
            msum += Ls[r * 65 + e];
            cnt  += (s_eid[r] == e);
        }
        g_me[b * NEXP + e]  = msum;
        g_cnt[b * NEXP + e] = cnt;
    }
}

// ---------------------------------------------------------------------------
// Kernel 3: exclusive scan over 128 blocks per expert; exp_counts, l_aux.
// ---------------------------------------------------------------------------
__global__ void scan_kernel(float* __restrict__ out)
{
    __shared__ float s_val[NEXP];
    const int e = threadIdx.x;   // 64 threads
    float me_tot = 0.f; int run = 0;
    for (int b = 0; b < NBLK64; b++) {
        g_offs[b * NEXP + e] = run;
        run    += g_cnt[b * NEXP + e];
        me_tot += g_me[b * NEXP + e];
    }
    out[1 + 2 * SEC + e] = (float)run;    // exp_counts (pre-drop)
    s_val[e] = me_tot * (float)run;
    __syncthreads();
    if (e == 0) {
        float acc = 0.f;
        for (int i = 0; i < NEXP; i++) acc += s_val[i];
        out[0] = acc * (1.f / 1048576.f);  // E/S^2 = 64/8192^2
    }
}

// ---------------------------------------------------------------------------
// Kernel 4: resolve in-order rank per token, scatter combine/dispatch.
// ---------------------------------------------------------------------------
__global__ void scatter_kernel(float* __restrict__ out)
{
    __shared__ int   s_eid[64];
    __shared__ float s_g[64];
    const int b = blockIdx.x;
    const int i = threadIdx.x;       // 64 threads
    const int s = b * 64 + i;
    s_eid[i] = g_eid[s];
    s_g[i]   = g_gate[s];
    __syncthreads();
    const int e = s_eid[i];
    int rank = g_offs[b * NEXP + e];
    for (int j = 0; j < i; j++) rank += (s_eid[j] == e);
    if (rank < CAP) {
        size_t base = (size_t)s * (NEXP * CAP) + (size_t)e * CAP + rank;
        out[1 + base]       = s_g[i];   // combine_weights
        out[1 + SEC + base] = 1.0f;     // dispatch_mask
    }
}

// ---------------------------------------------------------------------------
extern "C" void kernel_launch(void* const* d_in, const int* in_sizes, int n_in,
                              void* d_out, int out_size)
{
    const float* x  = (const float*)d_in[0];
    const float* wg = (const float*)d_in[1];
    float* out = (float*)d_out;

    gemm_zero_kernel<<<GRID_G, THREADS>>>(x, wg, out);
    gate_kernel<<<NBLK64, 256>>>();
    scan_kernel<<<1, NEXP>>>(out);
    scatter_kernel<<<NBLK64, 64>>>(out);
}